// round 16
// baseline (speedup 1.0000x reference)
#include <cuda_runtime.h>
#include <cstdint>

// Problem constants
#define TT 512
#define BB 128
#define HH 1024
#define SIGMA_REC 0.15811388300841897f   // sqrt(2/0.2)*0.05

// Grid / threads: 128 CTAs (4 row-blocks x 32 col-blocks), 256 threads, 1 CTA/SM.
// Warp w owns rows w*4..w*4+4 (warp-private A), all 32 cols, full K.
// Lane = (kg 0..7, cg 0..3): kg = K-split-by-8 (pairs == kg mod 8), cg = 8-col group.
#define NCTA 128
#define NTHREADS 256
#define CK 128
#define NCHUNK (HH / CK)        // 8
#define PAIRS_PER_CHUNK (CK/2)  // 64

// SMEM (floats)
// W: [512 pairs][68]; pair-row = 4 XOR-rotated 16-float cg-blocks (slot=(cg+p)&3) + 4 pad.
//    Conflict-free LDS.128: quad-bank = (p + 4*slot + i) mod 8 hits each bank exactly 4x.
#define WSTRIDE 68
#define W_FLOATS (512 * WSTRIDE)     // 34816
// A: per-warp double-buffered [2][4 rows][132]
#define ASTRIDE 132
#define AWARP (2 * 4 * ASTRIDE)      // 1056
#define A_OFF W_FLOATS
#define SMEM_FLOATS (A_OFF + 8 * AWARP)  // 43264
#define SMEM_BYTES (SMEM_FLOATS * 4)     // 173056 B (< 227 KB, 1 CTA/SM)

typedef unsigned long long ull;
#define FMA2(acc, a, w) asm("fma.rn.f32x2 %0, %1, %2, %0;" : "+l"(acc) : "l"(a), "l"(w))

__device__ unsigned g_flags[NCTA];

__global__ void rnn_init_kernel() {
    if (threadIdx.x < NCTA) g_flags[threadIdx.x] = 0u;
}

__device__ __forceinline__ void st_rel(unsigned* p, unsigned v) {
    asm volatile("st.global.release.gpu.u32 [%0], %1;" :: "l"(p), "r"(v) : "memory");
}
__device__ __forceinline__ unsigned ld_acq(const unsigned* p) {
    unsigned v;
    asm volatile("ld.global.acquire.gpu.u32 %0, [%1];" : "=r"(v) : "l"(p) : "memory");
    return v;
}

// All-CTA barrier (proven R10/R14): per-CTA release flag + every thread polls one flag.
__device__ __forceinline__ void grid_barrier(unsigned epoch) {
    __syncthreads();
    if (threadIdx.x == 0) st_rel(&g_flags[blockIdx.x], epoch);
    const unsigned idx = threadIdx.x & (NCTA - 1);
    while (ld_acq(&g_flags[idx]) < epoch) { }
    __syncthreads();
}

// Predicated half-compaction shuffle-reduce round over lane-xor `m`.
// Keeps (and compacts into v[0..half)) this lane's half, summing partner's.
#define RED_ROUND(half, m, hi) do {                                     \
    const bool kh_ = (hi);                                              \
    _Pragma("unroll")                                                   \
    for (int i_ = 0; i_ < (half); ++i_) {                               \
        const float send_ = kh_ ? v[i_] : v[i_ + (half)];               \
        const float recv_ = __shfl_xor_sync(0xffffffffu, send_, (m));   \
        v[i_] = (kh_ ? v[i_ + (half)] : v[i_]) + recv_;                 \
    }                                                                   \
} while (0)

__global__ void __launch_bounds__(NTHREADS, 1)
rnn_persistent_kernel(const float* __restrict__ inp,
                      const float* __restrict__ init_state,
                      const float* __restrict__ noise,
                      const float* __restrict__ wih,
                      const float* __restrict__ whh,
                      const float* __restrict__ bias,
                      float* __restrict__ out)
{
    extern __shared__ float sm[];
    float* sW = sm;
    float* sA = sm + A_OFF;

    const int tid  = threadIdx.x;
    const int cta  = blockIdx.x;
    const int row0 = (cta >> 5) * 32;
    const int col0 = (cta & 31) * 32;
    const int w    = tid >> 5;         // warp = row group (rows w*4..+4)
    const int lane = tid & 31;
    const int kg   = lane >> 2;        // 0..7  K-split lane
    const int cg   = lane & 3;         // 0..3  8-col group
    const int wrow0 = row0 + w * 4;

    // One-time: stage W strip, k-pair-interleaved inside XOR-rotated cg-blocks.
    for (int idx = tid; idx < HH * 32; idx += NTHREADS) {
        const int k = idx >> 5, c = idx & 31;
        const int p = k >> 1;
        sW[p * WSTRIDE + (((c >> 3) + p) & 3) * 16 + (c & 7) * 2 + (k & 1)] =
            whh[k * HH + col0 + c];
    }

    // Per-lane constants
    const int wslot = (cg + kg) & 3;   // (cg + p) & 3 is constant: p mod 4 == kg mod 4
    const int row_l = ((kg & 1) << 1) | ((kg >> 1) & 1);   // owned row after reduction
    const int orow  = wrow0 + row_l;
    const int ocol  = col0 + cg * 8 + ((kg >> 2) << 2);    // owned 4 cols

    float wa[4], wb[4], bb[4];
    #pragma unroll
    for (int j = 0; j < 4; ++j) {
        wa[j] = wih[ocol + j];
        wb[j] = wih[HH + ocol + j];
        bb[j] = bias[ocol + j];
    }

    // Staging mapping: lane -> (row s_row, quad s_q); stages quads s_q, s_q+8, +16, +24.
    const int s_row = lane >> 3;
    const int s_q   = lane & 7;
    float* aW = sA + w * AWARP;        // this warp's private double buffer

    // out[0] = initial_state; carry old state in registers.
    float4 old4 = *(const float4*)&init_state[orow * HH + ocol];
    *(float4*)&out[orow * HH + ocol] = old4;
    grid_barrier(1u);

    #pragma unroll 1
    for (int t = 0; t < TT; ++t) {
        const float* Ot = out + (size_t)t * (BB * HH);
        float*       On = out + (size_t)(t + 1) * (BB * HH);

        // Epilogue operands straight to registers; latency overlaps the GEMM.
        const float4 nz4 = *(const float4*)&noise[((size_t)t * BB + orow) * HH + ocol];
        const float2 iv2 = *(const float2*)&inp[((size_t)t * BB + orow) * 2];

        const float* srow = &Ot[(wrow0 + s_row) * HH];
        float* sdst = aW + s_row * ASTRIDE;

        // Stage chunk 0 into buffer 0 (warp-private -> __syncwarp only)
        {
            float4 u0 = *(const float4*)&srow[(s_q     ) * 4];
            float4 u1 = *(const float4*)&srow[(s_q +  8) * 4];
            float4 u2 = *(const float4*)&srow[(s_q + 16) * 4];
            float4 u3 = *(const float4*)&srow[(s_q + 24) * 4];
            u0.x=fmaxf(u0.x,0.f); u0.y=fmaxf(u0.y,0.f); u0.z=fmaxf(u0.z,0.f); u0.w=fmaxf(u0.w,0.f);
            u1.x=fmaxf(u1.x,0.f); u1.y=fmaxf(u1.y,0.f); u1.z=fmaxf(u1.z,0.f); u1.w=fmaxf(u1.w,0.f);
            u2.x=fmaxf(u2.x,0.f); u2.y=fmaxf(u2.y,0.f); u2.z=fmaxf(u2.z,0.f); u2.w=fmaxf(u2.w,0.f);
            u3.x=fmaxf(u3.x,0.f); u3.y=fmaxf(u3.y,0.f); u3.z=fmaxf(u3.z,0.f); u3.w=fmaxf(u3.w,0.f);
            *(float4*)&sdst[(s_q     ) * 4] = u0;
            *(float4*)&sdst[(s_q +  8) * 4] = u1;
            *(float4*)&sdst[(s_q + 16) * 4] = u2;
            *(float4*)&sdst[(s_q + 24) * 4] = u3;
        }
        __syncwarp();

        ull acc[4][8];
        #pragma unroll
        for (int r = 0; r < 4; ++r)
            #pragma unroll
            for (int c = 0; c < 8; ++c) acc[r][c] = 0ull;

        #pragma unroll 1
        for (int ck = 0; ck < NCHUNK; ++ck) {
            // Prefetch next chunk (warp-private buffer; safe by program order + syncwarp)
            float4 u0, u1, u2, u3;
            if (ck < NCHUNK - 1) {
                const int kb = (ck + 1) * CK;
                u0 = *(const float4*)&srow[kb + (s_q     ) * 4];
                u1 = *(const float4*)&srow[kb + (s_q +  8) * 4];
                u2 = *(const float4*)&srow[kb + (s_q + 16) * 4];
                u3 = *(const float4*)&srow[kb + (s_q + 24) * 4];
            }

            const float* aB = aW + (ck & 1) * (4 * ASTRIDE);
            const float* wB = sW + (size_t)(ck * PAIRS_PER_CHUNK) * WSTRIDE + wslot * 16;
            #pragma unroll
            for (int j = 0; j < 8; ++j) {
                const int pl = 8 * j + kg;                 // local pair index
                const float* ap = aB + 2 * pl;
                const ull a0 = *(const ull*)(ap);
                const ull a1 = *(const ull*)(ap + ASTRIDE);
                const ull a2 = *(const ull*)(ap + 2 * ASTRIDE);
                const ull a3 = *(const ull*)(ap + 3 * ASTRIDE);
                const float* wp = wB + (size_t)pl * WSTRIDE;
                const ulonglong2 wv0 = *(const ulonglong2*)(wp);
                const ulonglong2 wv1 = *(const ulonglong2*)(wp + 4);
                const ulonglong2 wv2 = *(const ulonglong2*)(wp + 8);
                const ulonglong2 wv3 = *(const ulonglong2*)(wp + 12);
                FMA2(acc[0][0], a0, wv0.x); FMA2(acc[0][1], a0, wv0.y);
                FMA2(acc[0][2], a0, wv1.x); FMA2(acc[0][3], a0, wv1.y);
                FMA2(acc[0][4], a0, wv2.x); FMA2(acc[0][5], a0, wv2.y);
                FMA2(acc[0][6], a0, wv3.x); FMA2(acc[0][7], a0, wv3.y);
                FMA2(acc[1][0], a1, wv0.x); FMA2(acc[1][1], a1, wv0.y);
                FMA2(acc[1][2], a1, wv1.x); FMA2(acc[1][3], a1, wv1.y);
                FMA2(acc[1][4], a1, wv2.x); FMA2(acc[1][5], a1, wv2.y);
                FMA2(acc[1][6], a1, wv3.x); FMA2(acc[1][7], a1, wv3.y);
                FMA2(acc[2][0], a2, wv0.x); FMA2(acc[2][1], a2, wv0.y);
                FMA2(acc[2][2], a2, wv1.x); FMA2(acc[2][3], a2, wv1.y);
                FMA2(acc[2][4], a2, wv2.x); FMA2(acc[2][5], a2, wv2.y);
                FMA2(acc[2][6], a2, wv3.x); FMA2(acc[2][7], a2, wv3.y);
                FMA2(acc[3][0], a3, wv0.x); FMA2(acc[3][1], a3, wv0.y);
                FMA2(acc[3][2], a3, wv1.x); FMA2(acc[3][3], a3, wv1.y);
                FMA2(acc[3][4], a3, wv2.x); FMA2(acc[3][5], a3, wv2.y);
                FMA2(acc[3][6], a3, wv3.x); FMA2(acc[3][7], a3, wv3.y);
            }

            if (ck < NCHUNK - 1) {
                u0.x=fmaxf(u0.x,0.f); u0.y=fmaxf(u0.y,0.f); u0.z=fmaxf(u0.z,0.f); u0.w=fmaxf(u0.w,0.f);
                u1.x=fmaxf(u1.x,0.f); u1.y=fmaxf(u1.y,0.f); u1.z=fmaxf(u1.z,0.f); u1.w=fmaxf(u1.w,0.f);
                u2.x=fmaxf(u2.x,0.f); u2.y=fmaxf(u2.y,0.f); u2.z=fmaxf(u2.z,0.f); u2.w=fmaxf(u2.w,0.f);
                u3.x=fmaxf(u3.x,0.f); u3.y=fmaxf(u3.y,0.f); u3.z=fmaxf(u3.z,0.f); u3.w=fmaxf(u3.w,0.f);
                float* nd = aW + ((ck + 1) & 1) * (4 * ASTRIDE) + s_row * ASTRIDE;
                *(float4*)&nd[(s_q     ) * 4] = u0;
                *(float4*)&nd[(s_q +  8) * 4] = u1;
                *(float4*)&nd[(s_q + 16) * 4] = u2;
                *(float4*)&nd[(s_q + 24) * 4] = u3;
                __syncwarp();
            }
        }

        // Fold k-parity and flatten: v[r*8+c]
        float v[32];
        #pragma unroll
        for (int r = 0; r < 4; ++r)
            #pragma unroll
            for (int c = 0; c < 8; ++c) {
                unsigned lo, hi;
                asm("mov.b64 {%0, %1}, %2;" : "=r"(lo), "=r"(hi) : "l"(acc[r][c]));
                v[r * 8 + c] = __uint_as_float(lo) + __uint_as_float(hi);
            }

        // Reduce over the 8 kg lanes: 3 half-compaction rounds.
        RED_ROUND(16, 4,  (kg & 1) != 0);        // rows {0,1} vs {2,3}
        RED_ROUND(8,  8,  (kg & 2) != 0);        // row within pair
        RED_ROUND(4,  16, (kg & 4) != 0);        // cols 0..3 vs 4..7

        // Epilogue: every lane owns 4 outputs (orow, ocol..+3)
        float4 res;
        res.x = 0.8f * old4.x + 0.2f * (v[0] + iv2.x * wa[0] + iv2.y * wb[0] + bb[0] + SIGMA_REC * nz4.x);
        res.y = 0.8f * old4.y + 0.2f * (v[1] + iv2.x * wa[1] + iv2.y * wb[1] + bb[1] + SIGMA_REC * nz4.y);
        res.z = 0.8f * old4.z + 0.2f * (v[2] + iv2.x * wa[2] + iv2.y * wb[2] + bb[2] + SIGMA_REC * nz4.z);
        res.w = 0.8f * old4.w + 0.2f * (v[3] + iv2.x * wa[3] + iv2.y * wb[3] + bb[3] + SIGMA_REC * nz4.w);
        *(float4*)&On[orow * HH + ocol] = res;
        old4 = res;

        grid_barrier((unsigned)(t + 2));
    }
}

extern "C" void kernel_launch(void* const* d_in, const int* in_sizes, int n_in,
                              void* d_out, int out_size) {
    const float* inp   = (const float*)d_in[0];  // [512,128,2]
    const float* inis  = (const float*)d_in[1];  // [128,1024]
    const float* noise = (const float*)d_in[2];  // [512,128,1024]
    const float* wih   = (const float*)d_in[3];  // [2,1024]
    const float* whh   = (const float*)d_in[4];  // [1024,1024]
    const float* bias  = (const float*)d_in[5];  // [1,1024]
    float* out = (float*)d_out;                  // [513,128,1024]

    cudaFuncSetAttribute(rnn_persistent_kernel,
                         cudaFuncAttributeMaxDynamicSharedMemorySize, SMEM_BYTES);

    rnn_init_kernel<<<1, NCTA>>>();
    rnn_persistent_kernel<<<NCTA, NTHREADS, SMEM_BYTES>>>(inp, inis, noise, wih, whh, bias, out);
}

// round 17
// speedup vs baseline: 1.2963x; 1.2963x over previous
#include <cuda_runtime.h>
#include <cstdint>

// Problem constants
#define TT 512
#define BB 128
#define HH 1024
#define SIGMA_REC 0.15811388300841897f   // sqrt(2/0.2)*0.05

// 128 CTAs (4 row-blocks x 32 col-blocks), 256 threads, 1 CTA/SM.
// Warp tile: 8 rows x 16 cols (R+C minimal) -> warp w: rows (w>>1)*8, cols (w&1)*16.
// The two warps of pair pr=w>>1 share an 8-row A buffer (named barrier pr+1, 64 thr).
// Lane = (kg = lane&7: K-split by 8, cg = lane>>3: 4-col group). Thread tile 8r x 4c.
#define NCTA 128
#define NTHREADS 256
#define CK 128
#define NCHUNK (HH / CK)        // 8

// SMEM (floats)
// W: [512 pairs][68]: 64 floats = 32 cols k-pair-interleaved (c*2+parity) + 4 pad.
//    w-LDS.128 granule = (17*pg + 2cg + side*8 + m) mod 8 -> uniform, conflict-free.
#define WSTRIDE 68
#define W_FLOATS (512 * WSTRIDE)       // 34816
// A: per-pair double buffer, pair-interleaved: [2 buf][64 plc][20]
//    floats [plc][r*2+parity], r=0..7 -> 16 used + 4 pad.
//    a-LDS.128 granule = (5*plc + m) mod 8 -> 5*kg mod 8 bijective, conflict-free.
#define PSTRIDE 20
#define ABUF (64 * PSTRIDE)            // 1280
#define APAIR (2 * ABUF)               // 2560
#define A_OFF W_FLOATS
#define SMEM_FLOATS (A_OFF + 4 * APAIR)   // 45056
#define SMEM_BYTES (SMEM_FLOATS * 4)      // 180224 B (< 227 KB, 1 CTA/SM)

typedef unsigned long long ull;
#define FMA2(acc, a, w) asm("fma.rn.f32x2 %0, %1, %2, %0;" : "+l"(acc) : "l"(a), "l"(w))

__device__ unsigned g_flags[NCTA];

__global__ void rnn_init_kernel() {
    if (threadIdx.x < NCTA) g_flags[threadIdx.x] = 0u;
}

__device__ __forceinline__ void st_rel(unsigned* p, unsigned v) {
    asm volatile("st.global.release.gpu.u32 [%0], %1;" :: "l"(p), "r"(v) : "memory");
}
__device__ __forceinline__ unsigned ld_acq(const unsigned* p) {
    unsigned v;
    asm volatile("ld.global.acquire.gpu.u32 %0, [%1];" : "=r"(v) : "l"(p) : "memory");
    return v;
}

// All-CTA barrier (proven): per-CTA release flag + every thread polls one flag.
__device__ __forceinline__ void grid_barrier(unsigned epoch) {
    __syncthreads();
    if (threadIdx.x == 0) st_rel(&g_flags[blockIdx.x], epoch);
    const unsigned idx = threadIdx.x & (NCTA - 1);
    while (ld_acq(&g_flags[idx]) < epoch) { }
    __syncthreads();
}

// Pair-scoped barrier: 64 threads (2 warps) on named barrier id.
#define PAIR_BAR(id) asm volatile("bar.sync %0, 64;" :: "r"(id) : "memory")

// Predicated half-compaction shuffle-reduce round over lane-xor m (proven R16).
#define RED_ROUND(half, m, hi) do {                                     \
    const bool kh_ = (hi);                                              \
    _Pragma("unroll")                                                   \
    for (int i_ = 0; i_ < (half); ++i_) {                               \
        const float send_ = kh_ ? v[i_] : v[i_ + (half)];               \
        const float recv_ = __shfl_xor_sync(0xffffffffu, send_, (m));   \
        v[i_] = (kh_ ? v[i_ + (half)] : v[i_]) + recv_;                 \
    }                                                                   \
} while (0)

__global__ void __launch_bounds__(NTHREADS, 1)
rnn_persistent_kernel(const float* __restrict__ inp,
                      const float* __restrict__ init_state,
                      const float* __restrict__ noise,
                      const float* __restrict__ wih,
                      const float* __restrict__ whh,
                      const float* __restrict__ bias,
                      float* __restrict__ out)
{
    extern __shared__ float sm[];
    float* sW = sm;
    float* sA = sm + A_OFF;

    const int tid  = threadIdx.x;
    const int cta  = blockIdx.x;
    const int row0 = (cta >> 5) * 32;
    const int col0 = (cta & 31) * 32;
    const int w    = tid >> 5;
    const int lane = tid & 31;
    const int pr   = w >> 1;          // pair 0..3: rows pr*8..+8
    const int side = w & 1;           // cols side*16..+16
    const int kg   = lane & 7;        // K-split lane
    const int cg   = lane >> 3;       // 4-col group
    const int prow0 = row0 + pr * 8;

    // One-time: stage W strip, k-pair-interleaved
    for (int idx = tid; idx < HH * 32; idx += NTHREADS) {
        const int k = idx >> 5, c = idx & 31;
        sW[(k >> 1) * WSTRIDE + c * 2 + (k & 1)] = whh[k * HH + col0 + c];
    }

    // Owned outputs after reduction: 1 row x 4 cols per lane.
    const int rowl = 4 * (kg & 1) + 2 * ((kg >> 1) & 1) + ((kg >> 2) & 1);
    const int orow = prow0 + rowl;
    const int ocol = col0 + side * 16 + cg * 4;

    float wa[4], wb[4], bb[4];
    #pragma unroll
    for (int j = 0; j < 4; ++j) {
        wa[j] = wih[ocol + j];
        wb[j] = wih[HH + ocol + j];
        bb[j] = bias[ocol + j];
    }

    // Staging mapping: pair-local thread lt stages row lt>>3, quads (lt&7)+8m.
    const int lt   = tid & 63;
    const int srow = lt >> 3;
    const int sq   = lt & 7;
    float* aP = sA + pr * APAIR;
    const int barid = pr + 1;

    // out[0] = initial_state; carry old state in registers.
    float4 old4 = *(const float4*)&init_state[orow * HH + ocol];
    *(float4*)&out[orow * HH + ocol] = old4;
    grid_barrier(1u);

    #pragma unroll 1
    for (int t = 0; t < TT; ++t) {
        const float* Ot = out + (size_t)t * (BB * HH);
        float*       On = out + (size_t)(t + 1) * (BB * HH);

        // Epilogue operands to registers; latency overlaps the GEMM.
        const float4 nz4 = *(const float4*)&noise[((size_t)t * BB + orow) * HH + ocol];
        const float2 iv2 = *(const float2*)&inp[((size_t)t * BB + orow) * 2];

        const float* srcRow = &Ot[(prow0 + srow) * HH];

        // Stage chunk 0 into buffer 0: relu, scatter to pair-interleaved layout.
        #pragma unroll
        for (int m = 0; m < 4; ++m) {
            float4 u = *(const float4*)&srcRow[sq * 4 + 32 * m];
            u.x = fmaxf(u.x, 0.f); u.y = fmaxf(u.y, 0.f);
            u.z = fmaxf(u.z, 0.f); u.w = fmaxf(u.w, 0.f);
            const int qm = sq + 8 * m;            // quad -> pairs 2qm, 2qm+1
            *(float2*)&aP[(2 * qm)     * PSTRIDE + srow * 2] = make_float2(u.x, u.y);
            *(float2*)&aP[(2 * qm + 1) * PSTRIDE + srow * 2] = make_float2(u.z, u.w);
        }
        PAIR_BAR(barid);

        ull acc[8][4];
        #pragma unroll
        for (int r = 0; r < 8; ++r)
            #pragma unroll
            for (int c = 0; c < 4; ++c) acc[r][c] = 0ull;

        #pragma unroll 1
        for (int ck = 0; ck < NCHUNK; ++ck) {
            // Prefetch next chunk from global (LDG latency hidden under j-loop)
            float4 u0, u1, u2, u3;
            if (ck < NCHUNK - 1) {
                const int kb = (ck + 1) * CK;
                u0 = *(const float4*)&srcRow[kb + sq * 4];
                u1 = *(const float4*)&srcRow[kb + sq * 4 + 32];
                u2 = *(const float4*)&srcRow[kb + sq * 4 + 64];
                u3 = *(const float4*)&srcRow[kb + sq * 4 + 96];
            }

            const float* aB = aP + (ck & 1) * ABUF;
            const float* wB = sW + (size_t)(ck * 64) * WSTRIDE + side * 32 + cg * 8;
            #pragma unroll
            for (int j = 0; j < 8; ++j) {
                const int plc = 8 * j + kg;
                // a: 4x LDS.128, each = pairs for rows {2m, 2m+1}; 4-way cg bcast
                const float* ap = aB + plc * PSTRIDE;
                const ulonglong2 av0 = *(const ulonglong2*)(ap);
                const ulonglong2 av1 = *(const ulonglong2*)(ap + 4);
                const ulonglong2 av2 = *(const ulonglong2*)(ap + 8);
                const ulonglong2 av3 = *(const ulonglong2*)(ap + 12);
                // w: 2x LDS.128 = k-pairs for 4 cols
                const float* wp = wB + (size_t)plc * WSTRIDE;
                const ulonglong2 wv0 = *(const ulonglong2*)(wp);
                const ulonglong2 wv1 = *(const ulonglong2*)(wp + 4);
                FMA2(acc[0][0], av0.x, wv0.x); FMA2(acc[0][1], av0.x, wv0.y);
                FMA2(acc[0][2], av0.x, wv1.x); FMA2(acc[0][3], av0.x, wv1.y);
                FMA2(acc[1][0], av0.y, wv0.x); FMA2(acc[1][1], av0.y, wv0.y);
                FMA2(acc[1][2], av0.y, wv1.x); FMA2(acc[1][3], av0.y, wv1.y);
                FMA2(acc[2][0], av1.x, wv0.x); FMA2(acc[2][1], av1.x, wv0.y);
                FMA2(acc[2][2], av1.x, wv1.x); FMA2(acc[2][3], av1.x, wv1.y);
                FMA2(acc[3][0], av1.y, wv0.x); FMA2(acc[3][1], av1.y, wv0.y);
                FMA2(acc[3][2], av1.y, wv1.x); FMA2(acc[3][3], av1.y, wv1.y);
                FMA2(acc[4][0], av2.x, wv0.x); FMA2(acc[4][1], av2.x, wv0.y);
                FMA2(acc[4][2], av2.x, wv1.x); FMA2(acc[4][3], av2.x, wv1.y);
                FMA2(acc[5][0], av2.y, wv0.x); FMA2(acc[5][1], av2.y, wv0.y);
                FMA2(acc[5][2], av2.y, wv1.x); FMA2(acc[5][3], av2.y, wv1.y);
                FMA2(acc[6][0], av3.x, wv0.x); FMA2(acc[6][1], av3.x, wv0.y);
                FMA2(acc[6][2], av3.x, wv1.x); FMA2(acc[6][3], av3.x, wv1.y);
                FMA2(acc[7][0], av3.y, wv0.x); FMA2(acc[7][1], av3.y, wv0.y);
                FMA2(acc[7][2], av3.y, wv1.x); FMA2(acc[7][3], av3.y, wv1.y);
            }

            if (ck < NCHUNK - 1) {
                u0.x=fmaxf(u0.x,0.f); u0.y=fmaxf(u0.y,0.f); u0.z=fmaxf(u0.z,0.f); u0.w=fmaxf(u0.w,0.f);
                u1.x=fmaxf(u1.x,0.f); u1.y=fmaxf(u1.y,0.f); u1.z=fmaxf(u1.z,0.f); u1.w=fmaxf(u1.w,0.f);
                u2.x=fmaxf(u2.x,0.f); u2.y=fmaxf(u2.y,0.f); u2.z=fmaxf(u2.z,0.f); u2.w=fmaxf(u2.w,0.f);
                u3.x=fmaxf(u3.x,0.f); u3.y=fmaxf(u3.y,0.f); u3.z=fmaxf(u3.z,0.f); u3.w=fmaxf(u3.w,0.f);
                float* nd = aP + ((ck + 1) & 1) * ABUF;
                *(float2*)&nd[(2 * sq)          * PSTRIDE + srow * 2] = make_float2(u0.x, u0.y);
                *(float2*)&nd[(2 * sq + 1)      * PSTRIDE + srow * 2] = make_float2(u0.z, u0.w);
                *(float2*)&nd[(2 * (sq+8))      * PSTRIDE + srow * 2] = make_float2(u1.x, u1.y);
                *(float2*)&nd[(2 * (sq+8) + 1)  * PSTRIDE + srow * 2] = make_float2(u1.z, u1.w);
                *(float2*)&nd[(2 * (sq+16))     * PSTRIDE + srow * 2] = make_float2(u2.x, u2.y);
                *(float2*)&nd[(2 * (sq+16) + 1) * PSTRIDE + srow * 2] = make_float2(u2.z, u2.w);
                *(float2*)&nd[(2 * (sq+24))     * PSTRIDE + srow * 2] = make_float2(u3.x, u3.y);
                *(float2*)&nd[(2 * (sq+24) + 1) * PSTRIDE + srow * 2] = make_float2(u3.z, u3.w);
                PAIR_BAR(barid);
            }
        }

        // Fold k-parity and flatten: v[r*4+c]
        float v[32];
        #pragma unroll
        for (int r = 0; r < 8; ++r)
            #pragma unroll
            for (int c = 0; c < 4; ++c) {
                unsigned lo, hi;
                asm("mov.b64 {%0, %1}, %2;" : "=r"(lo), "=r"(hi) : "l"(acc[r][c]));
                v[r * 4 + c] = __uint_as_float(lo) + __uint_as_float(hi);
            }

        // Reduce over the 8 kg lanes: rows 0-3/4-7, then pairs, then single row.
        RED_ROUND(16, 1, (kg & 1) != 0);
        RED_ROUND(8,  2, (kg & 2) != 0);
        RED_ROUND(4,  4, (kg & 4) != 0);

        // Epilogue: every lane owns (orow, ocol..+3)
        float4 res;
        res.x = 0.8f * old4.x + 0.2f * (v[0] + iv2.x * wa[0] + iv2.y * wb[0] + bb[0] + SIGMA_REC * nz4.x);
        res.y = 0.8f * old4.y + 0.2f * (v[1] + iv2.x * wa[1] + iv2.y * wb[1] + bb[1] + SIGMA_REC * nz4.y);
        res.z = 0.8f * old4.z + 0.2f * (v[2] + iv2.x * wa[2] + iv2.y * wb[2] + bb[2] + SIGMA_REC * nz4.z);
        res.w = 0.8f * old4.w + 0.2f * (v[3] + iv2.x * wa[3] + iv2.y * wb[3] + bb[3] + SIGMA_REC * nz4.w);
        *(float4*)&On[orow * HH + ocol] = res;
        old4 = res;

        grid_barrier((unsigned)(t + 2));
    }
}

extern "C" void kernel_launch(void* const* d_in, const int* in_sizes, int n_in,
                              void* d_out, int out_size) {
    const float* inp   = (const float*)d_in[0];  // [512,128,2]
    const float* inis  = (const float*)d_in[1];  // [128,1024]
    const float* noise = (const float*)d_in[2];  // [512,128,1024]
    const float* wih   = (const float*)d_in[3];  // [2,1024]
    const float* whh   = (const float*)d_in[4];  // [1024,1024]
    const float* bias  = (const float*)d_in[5];  // [1,1024]
    float* out = (float*)d_out;                  // [513,128,1024]

    cudaFuncSetAttribute(rnn_persistent_kernel,
                         cudaFuncAttributeMaxDynamicSharedMemorySize, SMEM_BYTES);

    rnn_init_kernel<<<1, NCTA>>>();
    rnn_persistent_kernel<<<NCTA, NTHREADS, SMEM_BYTES>>>(inp, inis, noise, wih, whh, bias, out);
}